// round 14
// baseline (speedup 1.0000x reference)
#include <cuda_runtime.h>
#include <cstdint>

#define NPTS   8192
#define NB     4
#define NC     1024
#define KNN    32
#define DFEAT  13
#define NROWS  (NB*NC*KNN)          // 131072
#define CENT_FLOATS (NB*NC*3)       // 12288
#define CSZ    4                    // FPS cluster size (CTAs per batch)
#define PPC    (NPTS/CSZ)           // 2048 points per CTA

static __device__ float  g_x2[NB*NPTS];
static __device__ float  g_grouped[(size_t)NROWS*16];
static __device__ float  g_y0[(size_t)NROWS*64];
static __device__ float  g_y1[(size_t)NROWS*64];
static __device__ float  g_y2[(size_t)NROWS*128];
// stats: [0:64) s0 [64:128) ss0 [128:192) s1 [192:256) ss1 [256:384) s2 [384:512) ss2
static __device__ double g_stats[512];

__device__ __forceinline__ float f_inf() { return __int_as_float(0x7f800000); }

// packed f32x2 ops (per-lane IEEE rn, identical to scalar __fadd_rn/__fmul_rn).
#define MUL_F32X2(out, a, b) asm("mul.rn.f32x2 %0, %1, %2;" : "=l"(out) : "l"(a), "l"(b))
#define ADD_F32X2(out, a, b) asm("add.rn.f32x2 %0, %1, %2;" : "=l"(out) : "l"(a), "l"(b))
#define PACK_F32X2(out, lo, hi) asm("mov.b64 %0, {%1, %2};" : "=l"(out) : "r"(lo), "r"(hi))
#define UNPACK_F32X2(lo, hi, in) asm("mov.b64 {%0, %1}, %2;" : "=r"(lo), "=r"(hi) : "l"(in))

__device__ __forceinline__ uint32_t smem_u32(const void* p) {
    uint32_t a;
    asm("{ .reg .u64 t; cvta.to.shared.u64 t, %1; cvt.u32.u64 %0, t; }" : "=r"(a) : "l"(p));
    return a;
}

// ---------------- threefry2x32 (jax partitionable mode) ----------------
__device__ __forceinline__ uint32_t rotl32(uint32_t x, int d) { return (x << d) | (x >> (32 - d)); }

__device__ __forceinline__ void threefry2x32(uint32_t k0, uint32_t k1, uint32_t c0, uint32_t c1,
                                             uint32_t& o0, uint32_t& o1) {
    uint32_t ks0 = k0, ks1 = k1, ks2 = k0 ^ k1 ^ 0x1BD11BDAu;
    uint32_t x0 = c0 + ks0, x1 = c1 + ks1;
#define TF_R(r) { x0 += x1; x1 = rotl32(x1, r); x1 ^= x0; }
#define TF_A TF_R(13) TF_R(15) TF_R(26) TF_R(6)
#define TF_B TF_R(17) TF_R(29) TF_R(16) TF_R(24)
    TF_A; x0 += ks1; x1 += ks2 + 1u;
    TF_B; x0 += ks2; x1 += ks0 + 2u;
    TF_A; x0 += ks0; x1 += ks1 + 3u;
    TF_B; x0 += ks1; x1 += ks2 + 4u;
    TF_A; x0 += ks2; x1 += ks0 + 5u;
#undef TF_A
#undef TF_B
#undef TF_R
    o0 = x0; o1 = x1;
}

__global__ void zero_stats_kernel() {
    int i = threadIdx.x;
    if (i < 512) g_stats[i] = 0.0;
}

// ---------------- FPS: 4-CTA cluster per batch, 512 thr x 4 pts ----------------
// Same bit-exact math / sqrt-domain argmax / warp-local threshold as the proven
// single-CTA version. Cross-CTA all-reduce each iteration via DSMEM slot writes
// + mbarrier (release/acquire, cluster scope), double-buffered. No cluster.sync
// in the loop (keeps L1 warm for the centroid load).
__global__ __launch_bounds__(512, 1) __cluster_dims__(CSZ, 1, 1)
void fps_kernel(const float* __restrict__ coords, float* __restrict__ out_cent) {
    const int crank = blockIdx.x & (CSZ - 1);
    const int b = blockIdx.x / CSZ;
    const float* cb = coords + (size_t)b * NPTS * 3;
    const int tid = threadIdx.x;
    const int wid = tid >> 5, lane = tid & 31;
    const int pbase = crank * PPC;

    unsigned long long pxp[2], pyp[2], pzp[2];
    float dist[4];
#pragma unroll
    for (int t = 0; t < 4; t++) {
        int p = pbase + tid + t * 512;
        float x = cb[3 * p], y = cb[3 * p + 1], z = cb[3 * p + 2];
        dist[t] = f_inf();
        g_x2[b * NPTS + p] = __fadd_rn(__fadd_rn(__fmul_rn(x, x), __fmul_rn(y, y)),
                                       __fmul_rn(z, z));
    }
#pragma unroll
    for (int m = 0; m < 2; m++) {
        int p0 = pbase + tid + (2 * m) * 512, p1 = p0 + 512;
        PACK_F32X2(pxp[m], __float_as_uint(cb[3 * p0]),     __float_as_uint(cb[3 * p1]));
        PACK_F32X2(pyp[m], __float_as_uint(cb[3 * p0 + 1]), __float_as_uint(cb[3 * p1 + 1]));
        PACK_F32X2(pzp[m], __float_as_uint(cb[3 * p0 + 2]), __float_as_uint(cb[3 * p1 + 2]));
    }

    __shared__ unsigned long long smbar[2];      // double-buffered cluster barriers
    __shared__ unsigned long long sslot[CSZ];    // per-rank result slots
    __shared__ uint32_t shi[2][16], slo[2][16];

    const uint32_t mbar0 = smem_u32((const void*)smbar);
    const uint32_t slot0 = smem_u32((const void*)sslot);

    if (tid == 0) {
        asm volatile("mbarrier.init.shared.b64 [%0], %1;" :: "r"(mbar0), "r"(CSZ) : "memory");
        asm volatile("mbarrier.init.shared.b64 [%0], %1;" :: "r"(mbar0 + 8u), "r"(CSZ) : "memory");
    }
    asm volatile("barrier.cluster.arrive.aligned;" ::: "memory");
    asm volatile("barrier.cluster.wait.aligned;" ::: "memory");

    int f;
    {
        uint32_t k2a, k2b, o0, o1;
        threefry2x32(0u, 42u, 0u, 1u, k2a, k2b);
        threefry2x32(k2a, k2b, 0u, (uint32_t)b, o0, o1);
        f = (int)((o0 ^ o1) & 8191u);
    }

    for (int it = 0; it < NC; ++it) {
        const int buf = it & 1;
        const uint32_t par = (uint32_t)((it >> 1) & 1);
        float fx = cb[3 * f], fy = cb[3 * f + 1], fz = cb[3 * f + 2];  // L1 broadcast
        if (crank == 0 && tid == 0) {
            float* oc = out_cent + ((size_t)b * NC + it) * 3;
            oc[0] = fx; oc[1] = fy; oc[2] = fz;
        }
        unsigned long long nfx, nfy, nfz;
        {
            uint32_t nx = __float_as_uint(-fx), ny = __float_as_uint(-fy), nz = __float_as_uint(-fz);
            PACK_F32X2(nfx, nx, nx); PACK_F32X2(nfy, ny, ny); PACK_F32X2(nfz, nz, nz);
        }

        // Phase A
        float mv = -1.0f;
#pragma unroll
        for (int m = 0; m < 2; m++) {
            unsigned long long dx, dy, dz, xx, yy, zz, s1, d2p;
            ADD_F32X2(dx, pxp[m], nfx);
            ADD_F32X2(dy, pyp[m], nfy);
            ADD_F32X2(dz, pzp[m], nfz);
            MUL_F32X2(xx, dx, dx);
            MUL_F32X2(yy, dy, dy);
            MUL_F32X2(zz, dz, dz);
            ADD_F32X2(s1, xx, yy);
            ADD_F32X2(d2p, s1, zz);
            uint32_t lo, hi;
            UNPACK_F32X2(lo, hi, d2p);
            float a = __uint_as_float(lo), c = __uint_as_float(hi);
            dist[2 * m]     = fminf(dist[2 * m], a);
            dist[2 * m + 1] = fminf(dist[2 * m + 1], c);
            mv = fmaxf(mv, dist[2 * m]);
            mv = fmaxf(mv, dist[2 * m + 1]);
        }
        uint32_t wmv = __reduce_max_sync(0xffffffffu, __float_as_uint(mv));
        uint32_t thr = (wmv >= 8u) ? (wmv - 8u) : 0u;
        float thr_f = __uint_as_float(thr);

        // Phase B
        uint32_t best = 0u; uint32_t bidx = 0x7fffffffu;
#pragma unroll
        for (int t = 0; t < 4; t++) {
            if (dist[t] >= thr_f) {
                uint32_t sb = __float_as_uint(__fsqrt_rn(dist[t]));
                if (sb > best) { best = sb; bidx = (uint32_t)(pbase + tid + t * 512); }
            }
        }
        uint32_t wmax = __reduce_max_sync(0xffffffffu, best);
        uint32_t cand = (best == wmax) ? bidx : 0xffffffffu;
        uint32_t widx = __reduce_min_sync(0xffffffffu, cand);
        if (lane == 0) { shi[buf][wid] = wmax; slo[buf][wid] = widx; }
        __syncthreads();
        if (wid == 0) {
            uint32_t v = (lane < 16) ? shi[buf][lane] : 0u;
            uint32_t m = __reduce_max_sync(0xffffffffu, v);
            uint32_t c = (v == m && lane < 16) ? slo[buf][lane] : 0xffffffffu;
            uint32_t g = __reduce_min_sync(0xffffffffu, c);
            if (lane == 0) {
                unsigned long long key = ((unsigned long long)m << 32) | (uint32_t)(~g);
                uint32_t myslot = slot0 + (uint32_t)(crank * 8);
                uint32_t mybar = mbar0 + (uint32_t)(buf * 8);
#pragma unroll
                for (int j = 0; j < CSZ; j++) {
                    uint32_t rs, rb;
                    asm volatile("mapa.shared::cluster.u32 %0, %1, %2;"
                                 : "=r"(rs) : "r"(myslot), "r"(j));
                    asm volatile("st.shared::cluster.u64 [%0], %1;"
                                 :: "r"(rs), "l"(key) : "memory");
                    asm volatile("mapa.shared::cluster.u32 %0, %1, %2;"
                                 : "=r"(rb) : "r"(mybar), "r"(j));
                    asm volatile("mbarrier.arrive.release.cluster.shared::cluster.b64 _, [%0];"
                                 :: "r"(rb) : "memory");
                }
            }
        }
        // all threads wait on local barrier (acquire, cluster scope)
        {
            uint32_t done;
            uint32_t baddr = mbar0 + (uint32_t)(buf * 8);
            do {
                asm volatile(
                    "{\n\t.reg .pred p;\n\t"
                    "mbarrier.try_wait.parity.acquire.cluster.shared::cta.b64 p, [%1], %2;\n\t"
                    "selp.b32 %0, 1, 0, p;\n\t}"
                    : "=r"(done) : "r"(baddr), "r"(par) : "memory");
            } while (!done);
        }
        unsigned long long k0 = sslot[0], k1 = sslot[1], k2 = sslot[2], k3 = sslot[3];
        unsigned long long ka = (k0 > k1) ? k0 : k1;
        unsigned long long kb = (k2 > k3) ? k2 : k3;
        unsigned long long km = (ka > kb) ? ka : kb;
        f = (int)(~(uint32_t)km & 0x1fffu);
    }
}

// ---------------- grouping: one block per (b,c) ----------------
__global__ __launch_bounds__(256) void group_kernel(const float* __restrict__ coords,
                                                    const float* __restrict__ features,
                                                    const float* __restrict__ cent,
                                                    float* __restrict__ grouped) {
    const int bc = blockIdx.x;
    const int b = bc >> 10;
    const int tid = threadIdx.x;
    const int wid = tid >> 5, lane = tid & 31;
    const float* cb = coords + (size_t)b * NPTS * 3;
    const float* fb = features + (size_t)b * NPTS * DFEAT;
    const float* x2b = g_x2 + b * NPTS;

    const float cx = cent[3 * bc], cy = cent[3 * bc + 1], cz = cent[3 * bc + 2];
    const float c2 = __fadd_rn(__fadd_rn(__fmul_rn(cx, cx), __fmul_rn(cy, cy)), __fmul_rn(cz, cz));
    const float r2 = 0.04f;

    __shared__ float sval[1024];
    __shared__ int sidx[1024];
    __shared__ int scnt;
    __shared__ int schosen[KNN];

    if (tid == 0) scnt = 0;
    __syncthreads();

    for (int n = tid; n < NPTS; n += 256) {
        float x = cb[3 * n], y = cb[3 * n + 1], z = cb[3 * n + 2];
        float dot = __fmaf_rn(cz, z, __fmaf_rn(cy, y, __fmul_rn(cx, x)));
        float d = __fadd_rn(__fmaf_rn(-2.0f, dot, c2), x2b[n]);
        if (d <= r2) {
            int p = atomicAdd(&scnt, 1);
            if (p < 1024) { sval[p] = d; sidx[p] = n; }
        }
    }
    __syncthreads();
    const int M = min(scnt, 1024);
    const int nsel = min(M, KNN);

    if (wid == 0) {
        for (int round = 0; round < nsel; round++) {
            float bv = f_inf(); int bn = 0x7fffffff; int bj = -1;
            for (int j = lane; j < M; j += 32) {
                float v = sval[j]; int n = sidx[j];
                if (v < bv || (v == bv && n < bn)) { bv = v; bn = n; bj = j; }
            }
            uint32_t vb = __float_as_uint(bv);
            vb = (vb & 0x80000000u) ? ~vb : (vb | 0x80000000u);
            uint32_t vmin = __reduce_min_sync(0xffffffffu, vb);
            uint32_t cand = (vb == vmin) ? (uint32_t)bn : 0xffffffffu;
            uint32_t nwin = __reduce_min_sync(0xffffffffu, cand);
            if (vb == vmin && (uint32_t)bn == nwin) sval[bj] = f_inf();
            if (lane == 0) schosen[round] = (int)nwin;
            __syncwarp();
        }
    }
    __syncthreads();

    if (nsel < KNN && tid == 0) {
        int pos = nsel;
        for (int n = 0; n < NPTS && pos < KNN; n++) {
            float x = cb[3 * n], y = cb[3 * n + 1], z = cb[3 * n + 2];
            float dot = __fmaf_rn(cz, z, __fmaf_rn(cy, y, __fmul_rn(cx, x)));
            float d = __fadd_rn(__fmaf_rn(-2.0f, dot, c2), x2b[n]);
            if (!(d <= r2)) schosen[pos++] = n;
        }
    }
    __syncthreads();

    for (int t = tid; t < KNN * 16; t += 256) {
        int k = t >> 4, fc = t & 15;
        int n = schosen[k];
        float v;
        if (fc < 3) {
            float cen = (fc == 0) ? cx : ((fc == 1) ? cy : cz);
            v = cb[3 * n + fc] - cen;
        } else {
            v = fb[DFEAT * n + fc - 3];
        }
        grouped[((size_t)bc * KNN + k) * 16 + fc] = v;
    }
}

// ---------------- GEMM: register-tiled, k-major weights, k-unroll-4 float4 ----------------
template <int FIN, int FOUT, int ROWS, int SOFF, bool NORM>
__global__ __launch_bounds__(256) void gemm_kernel(const float* __restrict__ X,
                                                   const float* __restrict__ W,
                                                   const float* __restrict__ bias,
                                                   const float* __restrict__ gam,
                                                   const float* __restrict__ bet,
                                                   float* __restrict__ Y) {
    constexpr int VC = FOUT / 8;
    constexpr int RT = ROWS / 32;
    constexpr int XP = FIN + 4;

    __shared__ __align__(16) float sW[FIN * FOUT];
    __shared__ float sB[FOUT];
    __shared__ float sA[FIN], sCc[FIN];
    __shared__ __align__(16) float sX[ROWS * XP];

    const int tid = threadIdx.x;

    for (int i = tid; i < FIN * FOUT; i += 256) {
        int o = i / FIN, k = i % FIN;
        sW[k * FOUT + o] = W[i];
    }
    if (tid < FOUT) sB[tid] = bias[tid];
    if (NORM && tid < FIN) {
        double mu = g_stats[SOFF + tid] / (double)NROWS;
        double var = g_stats[SOFF + FIN + tid] / (double)NROWS - mu * mu;
        float a = (float)(1.0 / sqrt(var + 1e-5)) * gam[tid];
        sA[tid] = a;
        sCc[tid] = bet[tid] - (float)mu * a;
    }
    __syncthreads();

    const float4* xb4 = (const float4*)(X + (size_t)blockIdx.x * ROWS * FIN);
    for (int i = tid; i < ROWS * FIN / 4; i += 256) {
        float4 v = xb4[i];
        int row = i / (FIN / 4), c4 = i % (FIN / 4);
        if (NORM) {
            int ch = c4 * 4;
            v.x = fmaxf(fmaf(v.x, sA[ch],     sCc[ch]),     0.0f);
            v.y = fmaxf(fmaf(v.y, sA[ch + 1], sCc[ch + 1]), 0.0f);
            v.z = fmaxf(fmaf(v.z, sA[ch + 2], sCc[ch + 2]), 0.0f);
            v.w = fmaxf(fmaf(v.w, sA[ch + 3], sCc[ch + 3]), 0.0f);
        }
        *(float4*)&sX[row * XP + c4 * 4] = v;
    }
    __syncthreads();

    const int colg = tid & 7, rowg = tid >> 3;
    const int r0 = rowg * RT;

    float acc[RT][VC];
#pragma unroll
    for (int t = 0; t < RT; t++)
#pragma unroll
        for (int j = 0; j < VC; j++) acc[t][j] = sB[colg * VC + j];

#pragma unroll
    for (int k4 = 0; k4 < FIN; k4 += 4) {
        float4 xv[RT];
#pragma unroll
        for (int t = 0; t < RT; t++)
            xv[t] = *(const float4*)&sX[(r0 + t) * XP + k4];
#pragma unroll
        for (int j4 = 0; j4 < VC / 4; j4++) {
            float4 w0 = *(const float4*)&sW[(k4 + 0) * FOUT + colg * VC + j4 * 4];
            float4 w1 = *(const float4*)&sW[(k4 + 1) * FOUT + colg * VC + j4 * 4];
            float4 w2 = *(const float4*)&sW[(k4 + 2) * FOUT + colg * VC + j4 * 4];
            float4 w3 = *(const float4*)&sW[(k4 + 3) * FOUT + colg * VC + j4 * 4];
#pragma unroll
            for (int t = 0; t < RT; t++) {
                acc[t][j4*4+0] = fmaf(xv[t].x, w0.x, acc[t][j4*4+0]);
                acc[t][j4*4+1] = fmaf(xv[t].x, w0.y, acc[t][j4*4+1]);
                acc[t][j4*4+2] = fmaf(xv[t].x, w0.z, acc[t][j4*4+2]);
                acc[t][j4*4+3] = fmaf(xv[t].x, w0.w, acc[t][j4*4+3]);
                acc[t][j4*4+0] = fmaf(xv[t].y, w1.x, acc[t][j4*4+0]);
                acc[t][j4*4+1] = fmaf(xv[t].y, w1.y, acc[t][j4*4+1]);
                acc[t][j4*4+2] = fmaf(xv[t].y, w1.z, acc[t][j4*4+2]);
                acc[t][j4*4+3] = fmaf(xv[t].y, w1.w, acc[t][j4*4+3]);
                acc[t][j4*4+0] = fmaf(xv[t].z, w2.x, acc[t][j4*4+0]);
                acc[t][j4*4+1] = fmaf(xv[t].z, w2.y, acc[t][j4*4+1]);
                acc[t][j4*4+2] = fmaf(xv[t].z, w2.z, acc[t][j4*4+2]);
                acc[t][j4*4+3] = fmaf(xv[t].z, w2.w, acc[t][j4*4+3]);
                acc[t][j4*4+0] = fmaf(xv[t].w, w3.x, acc[t][j4*4+0]);
                acc[t][j4*4+1] = fmaf(xv[t].w, w3.y, acc[t][j4*4+1]);
                acc[t][j4*4+2] = fmaf(xv[t].w, w3.z, acc[t][j4*4+2]);
                acc[t][j4*4+3] = fmaf(xv[t].w, w3.w, acc[t][j4*4+3]);
            }
        }
    }
#pragma unroll
    for (int t = 0; t < RT; t++) {
        float* yr = Y + ((size_t)blockIdx.x * ROWS + r0 + t) * FOUT + colg * VC;
#pragma unroll
        for (int j4 = 0; j4 < VC / 4; j4++)
            ((float4*)yr)[j4] = make_float4(acc[t][j4 * 4], acc[t][j4 * 4 + 1],
                                            acc[t][j4 * 4 + 2], acc[t][j4 * 4 + 3]);
    }
}

// ---------------- per-channel sum / sumsq reduction ----------------
template <int F, int SOFF>
__global__ __launch_bounds__(256) void stats_kernel(const float* __restrict__ y) {
    constexpr int GROUPS = 256 / F;
    const int g = threadIdx.x / F, ch = threadIdx.x % F;
    const int base = blockIdx.x * 512;
    float s = 0.0f, ss = 0.0f;
    for (int r = base + g; r < base + 512; r += GROUPS) {
        float v = y[(size_t)r * F + ch];
        s += v;
        ss = fmaf(v, v, ss);
    }
    __shared__ float sh[256], sh2[256];
    sh[threadIdx.x] = s; sh2[threadIdx.x] = ss;
    __syncthreads();
    if (g == 0) {
#pragma unroll
        for (int gg = 1; gg < GROUPS; gg++) { s += sh[gg * F + ch]; ss += sh2[gg * F + ch]; }
        atomicAdd(&g_stats[SOFF + ch], (double)s);
        atomicAdd(&g_stats[SOFF + F + ch], (double)ss);
    }
}

// ---------------- BN+ReLU+maxpool over K ----------------
__global__ __launch_bounds__(128) void pool_kernel(const float* __restrict__ gam,
                                                   const float* __restrict__ bet,
                                                   float* __restrict__ out) {
    const int bc = blockIdx.x;
    const int o = threadIdx.x;
    double mu = g_stats[256 + o] / (double)NROWS;
    double var = g_stats[384 + o] / (double)NROWS - mu * mu;
    float a = (float)(1.0 / sqrt(var + 1e-5)) * gam[o];
    float c = bet[o] - (float)mu * a;
    float m = 0.0f;
#pragma unroll
    for (int k = 0; k < KNN; k++) {
        float v = g_y2[((size_t)bc * KNN + k) * 128 + o];
        v = fmaxf(fmaf(v, a, c), 0.0f);
        m = fmaxf(m, v);
    }
    out[CENT_FLOATS + (size_t)bc * 128 + o] = m;
}

extern "C" void kernel_launch(void* const* d_in, const int* in_sizes, int n_in,
                              void* d_out, int out_size) {
    // resolve inputs by element count (order-agnostic)
    int i_coords = -1, i_features = -1, i_w0 = -1, i_w1 = -1, i_w2 = -1;
    int idx64[6], n64 = 0;
    int idx128[3], n128 = 0;
    for (int i = 0; i < n_in; i++) {
        int s = in_sizes[i];
        if (s == 98304) i_coords = i;
        else if (s == 425984) i_features = i;
        else if (s == 1024) i_w0 = i;
        else if (s == 4096) i_w1 = i;
        else if (s == 8192) i_w2 = i;
        else if (s == 64 && n64 < 6) idx64[n64++] = i;
        else if (s == 128 && n128 < 3) idx128[n128++] = i;
    }

    int i_b0, i_g0, i_be0, i_b1, i_g1, i_be1, i_b2, i_g2, i_be2;
    if (i_coords == 0) {
        i_b0 = idx64[0]; i_g0 = idx64[1]; i_be0 = idx64[2];
        i_b1 = idx64[3]; i_g1 = idx64[4]; i_be1 = idx64[5];
        i_b2 = idx128[0]; i_g2 = idx128[1]; i_be2 = idx128[2];
    } else {
        i_b0 = idx64[0]; i_b1 = idx64[1]; i_be0 = idx64[2];
        i_be1 = idx64[3]; i_g0 = idx64[4]; i_g1 = idx64[5];
        i_b2 = idx128[0]; i_be2 = idx128[1]; i_g2 = idx128[2];
    }

    const float* coords   = (const float*)d_in[i_coords];
    const float* features = (const float*)d_in[i_features];
    const float* w0 = (const float*)d_in[i_w0];
    const float* b0 = (const float*)d_in[i_b0];
    const float* g0 = (const float*)d_in[i_g0];
    const float* be0 = (const float*)d_in[i_be0];
    const float* w1 = (const float*)d_in[i_w1];
    const float* b1 = (const float*)d_in[i_b1];
    const float* g1 = (const float*)d_in[i_g1];
    const float* be1 = (const float*)d_in[i_be1];
    const float* w2 = (const float*)d_in[i_w2];
    const float* b2 = (const float*)d_in[i_b2];
    const float* g2 = (const float*)d_in[i_g2];
    const float* be2 = (const float*)d_in[i_be2];
    float* out = (float*)d_out;

    (void)out_size;

    float* y0; float* y1; float* y2; float* gr;
    cudaGetSymbolAddress((void**)&gr, g_grouped);
    cudaGetSymbolAddress((void**)&y0, g_y0);
    cudaGetSymbolAddress((void**)&y1, g_y1);
    cudaGetSymbolAddress((void**)&y2, g_y2);

    zero_stats_kernel<<<1, 512>>>();
    fps_kernel<<<NB * CSZ, 512>>>(coords, out);
    group_kernel<<<NB * NC, 256>>>(coords, features, out, gr);

    gemm_kernel<16, 64, 64, 0, false><<<NROWS / 64, 256>>>(gr, w0, b0, nullptr, nullptr, y0);
    stats_kernel<64, 0><<<256, 256>>>(y0);
    gemm_kernel<64, 64, 64, 0, true><<<NROWS / 64, 256>>>(y0, w1, b1, g0, be0, y1);
    stats_kernel<64, 128><<<256, 256>>>(y1);
    gemm_kernel<64, 128, 32, 128, true><<<NROWS / 32, 256>>>(y1, w2, b2, g1, be1, y2);
    stats_kernel<128, 256><<<256, 256>>>(y2);
    pool_kernel<<<NB * NC, 128>>>(g2, be2, out);
}

// round 15
// speedup vs baseline: 1.1544x; 1.1544x over previous
#include <cuda_runtime.h>
#include <cstdint>

#define NPTS   8192
#define NB     4
#define NC     1024
#define KNN    32
#define DFEAT  13
#define NROWS  (NB*NC*KNN)          // 131072
#define CENT_FLOATS (NB*NC*3)       // 12288
#define CSZ    2                    // FPS cluster size (CTAs per batch)
#define PPC    (NPTS/CSZ)           // 4096 points per CTA

static __device__ float  g_x2[NB*NPTS];
static __device__ float  g_grouped[(size_t)NROWS*16];
static __device__ float  g_y0[(size_t)NROWS*64];
static __device__ float  g_y1[(size_t)NROWS*64];
static __device__ float  g_y2[(size_t)NROWS*128];
// stats: [0:64) s0 [64:128) ss0 [128:192) s1 [192:256) ss1 [256:384) s2 [384:512) ss2
static __device__ double g_stats[512];

__device__ __forceinline__ float f_inf() { return __int_as_float(0x7f800000); }

// packed f32x2 ops (per-lane IEEE rn, identical to scalar __fadd_rn/__fmul_rn).
#define MUL_F32X2(out, a, b) asm("mul.rn.f32x2 %0, %1, %2;" : "=l"(out) : "l"(a), "l"(b))
#define ADD_F32X2(out, a, b) asm("add.rn.f32x2 %0, %1, %2;" : "=l"(out) : "l"(a), "l"(b))
#define PACK_F32X2(out, lo, hi) asm("mov.b64 %0, {%1, %2};" : "=l"(out) : "r"(lo), "r"(hi))
#define UNPACK_F32X2(lo, hi, in) asm("mov.b64 {%0, %1}, %2;" : "=r"(lo), "=r"(hi) : "l"(in))

__device__ __forceinline__ uint32_t smem_u32(const void* p) {
    uint32_t a;
    asm("{ .reg .u64 t; cvta.to.shared.u64 t, %1; cvt.u32.u64 %0, t; }" : "=r"(a) : "l"(p));
    return a;
}

// ---------------- threefry2x32 (jax partitionable mode) ----------------
__device__ __forceinline__ uint32_t rotl32(uint32_t x, int d) { return (x << d) | (x >> (32 - d)); }

__device__ __forceinline__ void threefry2x32(uint32_t k0, uint32_t k1, uint32_t c0, uint32_t c1,
                                             uint32_t& o0, uint32_t& o1) {
    uint32_t ks0 = k0, ks1 = k1, ks2 = k0 ^ k1 ^ 0x1BD11BDAu;
    uint32_t x0 = c0 + ks0, x1 = c1 + ks1;
#define TF_R(r) { x0 += x1; x1 = rotl32(x1, r); x1 ^= x0; }
#define TF_A TF_R(13) TF_R(15) TF_R(26) TF_R(6)
#define TF_B TF_R(17) TF_R(29) TF_R(16) TF_R(24)
    TF_A; x0 += ks1; x1 += ks2 + 1u;
    TF_B; x0 += ks2; x1 += ks0 + 2u;
    TF_A; x0 += ks0; x1 += ks1 + 3u;
    TF_B; x0 += ks1; x1 += ks2 + 4u;
    TF_A; x0 += ks2; x1 += ks0 + 5u;
#undef TF_A
#undef TF_B
#undef TF_R
    o0 = x0; o1 = x1;
}

__global__ void zero_stats_kernel() {
    int i = threadIdx.x;
    if (i < 512) g_stats[i] = 0.0;
}

// ---------------- FPS: 2-CTA cluster per batch, 512 thr x 8 pts ----------------
// Bit-exact math / sqrt-domain argmax / warp-local threshold (proven). Cross-CTA
// all-reduce via DSMEM slot writes + double-buffered release/acquire mbarriers.
// Wait uses the suspend-hint try_wait (HW sleep) to avoid SMEM-port hammering.
__global__ __launch_bounds__(512, 1) __cluster_dims__(CSZ, 1, 1)
void fps_kernel(const float* __restrict__ coords, float* __restrict__ out_cent) {
    const int crank = blockIdx.x & (CSZ - 1);
    const int b = blockIdx.x / CSZ;
    const float* cb = coords + (size_t)b * NPTS * 3;
    const int tid = threadIdx.x;
    const int wid = tid >> 5, lane = tid & 31;
    const int pbase = crank * PPC;

    unsigned long long pxp[4], pyp[4], pzp[4];
    float dist[8];
#pragma unroll
    for (int t = 0; t < 8; t++) {
        int p = pbase + tid + t * 512;
        float x = cb[3 * p], y = cb[3 * p + 1], z = cb[3 * p + 2];
        dist[t] = f_inf();
        g_x2[b * NPTS + p] = __fadd_rn(__fadd_rn(__fmul_rn(x, x), __fmul_rn(y, y)),
                                       __fmul_rn(z, z));
    }
#pragma unroll
    for (int m = 0; m < 4; m++) {
        int p0 = pbase + tid + (2 * m) * 512, p1 = p0 + 512;
        PACK_F32X2(pxp[m], __float_as_uint(cb[3 * p0]),     __float_as_uint(cb[3 * p1]));
        PACK_F32X2(pyp[m], __float_as_uint(cb[3 * p0 + 1]), __float_as_uint(cb[3 * p1 + 1]));
        PACK_F32X2(pzp[m], __float_as_uint(cb[3 * p0 + 2]), __float_as_uint(cb[3 * p1 + 2]));
    }

    __shared__ unsigned long long smbar[2];      // double-buffered cluster barriers
    __shared__ unsigned long long sslot[CSZ];    // per-rank result slots
    __shared__ uint32_t shi[2][16], slo[2][16];

    const uint32_t mbar0 = smem_u32((const void*)smbar);
    const uint32_t slot0 = smem_u32((const void*)sslot);

    if (tid == 0) {
        asm volatile("mbarrier.init.shared.b64 [%0], %1;" :: "r"(mbar0), "r"(CSZ) : "memory");
        asm volatile("mbarrier.init.shared.b64 [%0], %1;" :: "r"(mbar0 + 8u), "r"(CSZ) : "memory");
    }
    asm volatile("barrier.cluster.arrive.aligned;" ::: "memory");
    asm volatile("barrier.cluster.wait.aligned;" ::: "memory");

    int f;
    {
        uint32_t k2a, k2b, o0, o1;
        threefry2x32(0u, 42u, 0u, 1u, k2a, k2b);
        threefry2x32(k2a, k2b, 0u, (uint32_t)b, o0, o1);
        f = (int)((o0 ^ o1) & 8191u);
    }

    for (int it = 0; it < NC; ++it) {
        const int buf = it & 1;
        const uint32_t par = (uint32_t)((it >> 1) & 1);
        float fx = cb[3 * f], fy = cb[3 * f + 1], fz = cb[3 * f + 2];  // L1 broadcast
        if (crank == 0 && tid == 0) {
            float* oc = out_cent + ((size_t)b * NC + it) * 3;
            oc[0] = fx; oc[1] = fy; oc[2] = fz;
        }
        unsigned long long nfx, nfy, nfz;
        {
            uint32_t nx = __float_as_uint(-fx), ny = __float_as_uint(-fy), nz = __float_as_uint(-fz);
            PACK_F32X2(nfx, nx, nx); PACK_F32X2(nfy, ny, ny); PACK_F32X2(nfz, nz, nz);
        }

        // Phase A
        float mv = -1.0f;
#pragma unroll
        for (int m = 0; m < 4; m++) {
            unsigned long long dx, dy, dz, xx, yy, zz, s1, d2p;
            ADD_F32X2(dx, pxp[m], nfx);
            ADD_F32X2(dy, pyp[m], nfy);
            ADD_F32X2(dz, pzp[m], nfz);
            MUL_F32X2(xx, dx, dx);
            MUL_F32X2(yy, dy, dy);
            MUL_F32X2(zz, dz, dz);
            ADD_F32X2(s1, xx, yy);
            ADD_F32X2(d2p, s1, zz);
            uint32_t lo, hi;
            UNPACK_F32X2(lo, hi, d2p);
            float a = __uint_as_float(lo), c = __uint_as_float(hi);
            dist[2 * m]     = fminf(dist[2 * m], a);
            dist[2 * m + 1] = fminf(dist[2 * m + 1], c);
            mv = fmaxf(mv, dist[2 * m]);
            mv = fmaxf(mv, dist[2 * m + 1]);
        }
        uint32_t wmv = __reduce_max_sync(0xffffffffu, __float_as_uint(mv));
        uint32_t thr = (wmv >= 8u) ? (wmv - 8u) : 0u;
        float thr_f = __uint_as_float(thr);

        // Phase B
        uint32_t best = 0u; uint32_t bidx = 0x7fffffffu;
#pragma unroll
        for (int t = 0; t < 8; t++) {
            if (dist[t] >= thr_f) {
                uint32_t sb = __float_as_uint(__fsqrt_rn(dist[t]));
                if (sb > best) { best = sb; bidx = (uint32_t)(pbase + tid + t * 512); }
            }
        }
        uint32_t wmax = __reduce_max_sync(0xffffffffu, best);
        uint32_t cand = (best == wmax) ? bidx : 0xffffffffu;
        uint32_t widx = __reduce_min_sync(0xffffffffu, cand);
        if (lane == 0) { shi[buf][wid] = wmax; slo[buf][wid] = widx; }
        __syncthreads();
        if (wid == 0) {
            uint32_t v = (lane < 16) ? shi[buf][lane] : 0u;
            uint32_t m = __reduce_max_sync(0xffffffffu, v);
            uint32_t c = (v == m && lane < 16) ? slo[buf][lane] : 0xffffffffu;
            uint32_t g = __reduce_min_sync(0xffffffffu, c);
            if (lane == 0) {
                unsigned long long key = ((unsigned long long)m << 32) | (uint32_t)(~g);
                uint32_t myslot = slot0 + (uint32_t)(crank * 8);
                uint32_t mybar = mbar0 + (uint32_t)(buf * 8);
#pragma unroll
                for (int j = 0; j < CSZ; j++) {
                    uint32_t rs, rb;
                    asm volatile("mapa.shared::cluster.u32 %0, %1, %2;"
                                 : "=r"(rs) : "r"(myslot), "r"(j));
                    asm volatile("st.shared::cluster.u64 [%0], %1;"
                                 :: "r"(rs), "l"(key) : "memory");
                    asm volatile("mapa.shared::cluster.u32 %0, %1, %2;"
                                 : "=r"(rb) : "r"(mybar), "r"(j));
                    asm volatile("mbarrier.arrive.release.cluster.shared::cluster.b64 _, [%0];"
                                 :: "r"(rb) : "memory");
                }
            }
        }
        // all threads wait on local barrier (acquire, cluster scope, HW-sleep hint)
        {
            uint32_t baddr = mbar0 + (uint32_t)(buf * 8);
            uint32_t done;
            asm volatile(
                "{\n\t.reg .pred p;\n\t"
                "mbarrier.try_wait.parity.acquire.cluster.shared::cta.b64 p, [%1], %2, 0x989680;\n\t"
                "selp.b32 %0, 1, 0, p;\n\t}"
                : "=r"(done) : "r"(baddr), "r"(par) : "memory");
            if (!done) {
                asm volatile(
                    "{\n\t.reg .pred P1;\n\t"
                    "WAIT_LOOP_%=:\n\t"
                    "mbarrier.try_wait.parity.acquire.cluster.shared::cta.b64 P1, [%0], %1, 0x989680;\n\t"
                    "@P1 bra.uni WAIT_DONE_%=;\n\t"
                    "bra.uni WAIT_LOOP_%=;\n\t"
                    "WAIT_DONE_%=:\n\t}"
                    :: "r"(baddr), "r"(par) : "memory");
            }
        }
        unsigned long long k0 = sslot[0], k1 = sslot[1];
        unsigned long long km = (k0 > k1) ? k0 : k1;
        f = (int)(~(uint32_t)km & 0x1fffu);
    }
}

// ---------------- grouping: one block per (b,c) ----------------
__global__ __launch_bounds__(256) void group_kernel(const float* __restrict__ coords,
                                                    const float* __restrict__ features,
                                                    const float* __restrict__ cent,
                                                    float* __restrict__ grouped) {
    const int bc = blockIdx.x;
    const int b = bc >> 10;
    const int tid = threadIdx.x;
    const int wid = tid >> 5, lane = tid & 31;
    const float* cb = coords + (size_t)b * NPTS * 3;
    const float* fb = features + (size_t)b * NPTS * DFEAT;
    const float* x2b = g_x2 + b * NPTS;

    const float cx = cent[3 * bc], cy = cent[3 * bc + 1], cz = cent[3 * bc + 2];
    const float c2 = __fadd_rn(__fadd_rn(__fmul_rn(cx, cx), __fmul_rn(cy, cy)), __fmul_rn(cz, cz));
    const float r2 = 0.04f;

    __shared__ float sval[1024];
    __shared__ int sidx[1024];
    __shared__ int scnt;
    __shared__ int schosen[KNN];

    if (tid == 0) scnt = 0;
    __syncthreads();

    for (int n = tid; n < NPTS; n += 256) {
        float x = cb[3 * n], y = cb[3 * n + 1], z = cb[3 * n + 2];
        float dot = __fmaf_rn(cz, z, __fmaf_rn(cy, y, __fmul_rn(cx, x)));
        float d = __fadd_rn(__fmaf_rn(-2.0f, dot, c2), x2b[n]);
        if (d <= r2) {
            int p = atomicAdd(&scnt, 1);
            if (p < 1024) { sval[p] = d; sidx[p] = n; }
        }
    }
    __syncthreads();
    const int M = min(scnt, 1024);
    const int nsel = min(M, KNN);

    if (wid == 0) {
        for (int round = 0; round < nsel; round++) {
            float bv = f_inf(); int bn = 0x7fffffff; int bj = -1;
            for (int j = lane; j < M; j += 32) {
                float v = sval[j]; int n = sidx[j];
                if (v < bv || (v == bv && n < bn)) { bv = v; bn = n; bj = j; }
            }
            uint32_t vb = __float_as_uint(bv);
            vb = (vb & 0x80000000u) ? ~vb : (vb | 0x80000000u);
            uint32_t vmin = __reduce_min_sync(0xffffffffu, vb);
            uint32_t cand = (vb == vmin) ? (uint32_t)bn : 0xffffffffu;
            uint32_t nwin = __reduce_min_sync(0xffffffffu, cand);
            if (vb == vmin && (uint32_t)bn == nwin) sval[bj] = f_inf();
            if (lane == 0) schosen[round] = (int)nwin;
            __syncwarp();
        }
    }
    __syncthreads();

    if (nsel < KNN && tid == 0) {
        int pos = nsel;
        for (int n = 0; n < NPTS && pos < KNN; n++) {
            float x = cb[3 * n], y = cb[3 * n + 1], z = cb[3 * n + 2];
            float dot = __fmaf_rn(cz, z, __fmaf_rn(cy, y, __fmul_rn(cx, x)));
            float d = __fadd_rn(__fmaf_rn(-2.0f, dot, c2), x2b[n]);
            if (!(d <= r2)) schosen[pos++] = n;
        }
    }
    __syncthreads();

    for (int t = tid; t < KNN * 16; t += 256) {
        int k = t >> 4, fc = t & 15;
        int n = schosen[k];
        float v;
        if (fc < 3) {
            float cen = (fc == 0) ? cx : ((fc == 1) ? cy : cz);
            v = cb[3 * n + fc] - cen;
        } else {
            v = fb[DFEAT * n + fc - 3];
        }
        grouped[((size_t)bc * KNN + k) * 16 + fc] = v;
    }
}

// ---------------- GEMM: register-tiled, k-major weights, k-unroll-4 float4 ----------------
template <int FIN, int FOUT, int ROWS, int SOFF, bool NORM>
__global__ __launch_bounds__(256) void gemm_kernel(const float* __restrict__ X,
                                                   const float* __restrict__ W,
                                                   const float* __restrict__ bias,
                                                   const float* __restrict__ gam,
                                                   const float* __restrict__ bet,
                                                   float* __restrict__ Y) {
    constexpr int VC = FOUT / 8;
    constexpr int RT = ROWS / 32;
    constexpr int XP = FIN + 4;

    __shared__ __align__(16) float sW[FIN * FOUT];
    __shared__ float sB[FOUT];
    __shared__ float sA[FIN], sCc[FIN];
    __shared__ __align__(16) float sX[ROWS * XP];

    const int tid = threadIdx.x;

    for (int i = tid; i < FIN * FOUT; i += 256) {
        int o = i / FIN, k = i % FIN;
        sW[k * FOUT + o] = W[i];
    }
    if (tid < FOUT) sB[tid] = bias[tid];
    if (NORM && tid < FIN) {
        double mu = g_stats[SOFF + tid] / (double)NROWS;
        double var = g_stats[SOFF + FIN + tid] / (double)NROWS - mu * mu;
        float a = (float)(1.0 / sqrt(var + 1e-5)) * gam[tid];
        sA[tid] = a;
        sCc[tid] = bet[tid] - (float)mu * a;
    }
    __syncthreads();

    const float4* xb4 = (const float4*)(X + (size_t)blockIdx.x * ROWS * FIN);
    for (int i = tid; i < ROWS * FIN / 4; i += 256) {
        float4 v = xb4[i];
        int row = i / (FIN / 4), c4 = i % (FIN / 4);
        if (NORM) {
            int ch = c4 * 4;
            v.x = fmaxf(fmaf(v.x, sA[ch],     sCc[ch]),     0.0f);
            v.y = fmaxf(fmaf(v.y, sA[ch + 1], sCc[ch + 1]), 0.0f);
            v.z = fmaxf(fmaf(v.z, sA[ch + 2], sCc[ch + 2]), 0.0f);
            v.w = fmaxf(fmaf(v.w, sA[ch + 3], sCc[ch + 3]), 0.0f);
        }
        *(float4*)&sX[row * XP + c4 * 4] = v;
    }
    __syncthreads();

    const int colg = tid & 7, rowg = tid >> 3;
    const int r0 = rowg * RT;

    float acc[RT][VC];
#pragma unroll
    for (int t = 0; t < RT; t++)
#pragma unroll
        for (int j = 0; j < VC; j++) acc[t][j] = sB[colg * VC + j];

#pragma unroll
    for (int k4 = 0; k4 < FIN; k4 += 4) {
        float4 xv[RT];
#pragma unroll
        for (int t = 0; t < RT; t++)
            xv[t] = *(const float4*)&sX[(r0 + t) * XP + k4];
#pragma unroll
        for (int j4 = 0; j4 < VC / 4; j4++) {
            float4 w0 = *(const float4*)&sW[(k4 + 0) * FOUT + colg * VC + j4 * 4];
            float4 w1 = *(const float4*)&sW[(k4 + 1) * FOUT + colg * VC + j4 * 4];
            float4 w2 = *(const float4*)&sW[(k4 + 2) * FOUT + colg * VC + j4 * 4];
            float4 w3 = *(const float4*)&sW[(k4 + 3) * FOUT + colg * VC + j4 * 4];
#pragma unroll
            for (int t = 0; t < RT; t++) {
                acc[t][j4*4+0] = fmaf(xv[t].x, w0.x, acc[t][j4*4+0]);
                acc[t][j4*4+1] = fmaf(xv[t].x, w0.y, acc[t][j4*4+1]);
                acc[t][j4*4+2] = fmaf(xv[t].x, w0.z, acc[t][j4*4+2]);
                acc[t][j4*4+3] = fmaf(xv[t].x, w0.w, acc[t][j4*4+3]);
                acc[t][j4*4+0] = fmaf(xv[t].y, w1.x, acc[t][j4*4+0]);
                acc[t][j4*4+1] = fmaf(xv[t].y, w1.y, acc[t][j4*4+1]);
                acc[t][j4*4+2] = fmaf(xv[t].y, w1.z, acc[t][j4*4+2]);
                acc[t][j4*4+3] = fmaf(xv[t].y, w1.w, acc[t][j4*4+3]);
                acc[t][j4*4+0] = fmaf(xv[t].z, w2.x, acc[t][j4*4+0]);
                acc[t][j4*4+1] = fmaf(xv[t].z, w2.y, acc[t][j4*4+1]);
                acc[t][j4*4+2] = fmaf(xv[t].z, w2.z, acc[t][j4*4+2]);
                acc[t][j4*4+3] = fmaf(xv[t].z, w2.w, acc[t][j4*4+3]);
                acc[t][j4*4+0] = fmaf(xv[t].w, w3.x, acc[t][j4*4+0]);
                acc[t][j4*4+1] = fmaf(xv[t].w, w3.y, acc[t][j4*4+1]);
                acc[t][j4*4+2] = fmaf(xv[t].w, w3.z, acc[t][j4*4+2]);
                acc[t][j4*4+3] = fmaf(xv[t].w, w3.w, acc[t][j4*4+3]);
            }
        }
    }
#pragma unroll
    for (int t = 0; t < RT; t++) {
        float* yr = Y + ((size_t)blockIdx.x * ROWS + r0 + t) * FOUT + colg * VC;
#pragma unroll
        for (int j4 = 0; j4 < VC / 4; j4++)
            ((float4*)yr)[j4] = make_float4(acc[t][j4 * 4], acc[t][j4 * 4 + 1],
                                            acc[t][j4 * 4 + 2], acc[t][j4 * 4 + 3]);
    }
}

// ---------------- per-channel sum / sumsq reduction ----------------
template <int F, int SOFF>
__global__ __launch_bounds__(256) void stats_kernel(const float* __restrict__ y) {
    constexpr int GROUPS = 256 / F;
    const int g = threadIdx.x / F, ch = threadIdx.x % F;
    const int base = blockIdx.x * 512;
    float s = 0.0f, ss = 0.0f;
    for (int r = base + g; r < base + 512; r += GROUPS) {
        float v = y[(size_t)r * F + ch];
        s += v;
        ss = fmaf(v, v, ss);
    }
    __shared__ float sh[256], sh2[256];
    sh[threadIdx.x] = s; sh2[threadIdx.x] = ss;
    __syncthreads();
    if (g == 0) {
#pragma unroll
        for (int gg = 1; gg < GROUPS; gg++) { s += sh[gg * F + ch]; ss += sh2[gg * F + ch]; }
        atomicAdd(&g_stats[SOFF + ch], (double)s);
        atomicAdd(&g_stats[SOFF + F + ch], (double)ss);
    }
}

// ---------------- BN+ReLU+maxpool over K ----------------
__global__ __launch_bounds__(128) void pool_kernel(const float* __restrict__ gam,
                                                   const float* __restrict__ bet,
                                                   float* __restrict__ out) {
    const int bc = blockIdx.x;
    const int o = threadIdx.x;
    double mu = g_stats[256 + o] / (double)NROWS;
    double var = g_stats[384 + o] / (double)NROWS - mu * mu;
    float a = (float)(1.0 / sqrt(var + 1e-5)) * gam[o];
    float c = bet[o] - (float)mu * a;
    float m = 0.0f;
#pragma unroll
    for (int k = 0; k < KNN; k++) {
        float v = g_y2[((size_t)bc * KNN + k) * 128 + o];
        v = fmaxf(fmaf(v, a, c), 0.0f);
        m = fmaxf(m, v);
    }
    out[CENT_FLOATS + (size_t)bc * 128 + o] = m;
}

extern "C" void kernel_launch(void* const* d_in, const int* in_sizes, int n_in,
                              void* d_out, int out_size) {
    // resolve inputs by element count (order-agnostic)
    int i_coords = -1, i_features = -1, i_w0 = -1, i_w1 = -1, i_w2 = -1;
    int idx64[6], n64 = 0;
    int idx128[3], n128 = 0;
    for (int i = 0; i < n_in; i++) {
        int s = in_sizes[i];
        if (s == 98304) i_coords = i;
        else if (s == 425984) i_features = i;
        else if (s == 1024) i_w0 = i;
        else if (s == 4096) i_w1 = i;
        else if (s == 8192) i_w2 = i;
        else if (s == 64 && n64 < 6) idx64[n64++] = i;
        else if (s == 128 && n128 < 3) idx128[n128++] = i;
    }

    int i_b0, i_g0, i_be0, i_b1, i_g1, i_be1, i_b2, i_g2, i_be2;
    if (i_coords == 0) {
        i_b0 = idx64[0]; i_g0 = idx64[1]; i_be0 = idx64[2];
        i_b1 = idx64[3]; i_g1 = idx64[4]; i_be1 = idx64[5];
        i_b2 = idx128[0]; i_g2 = idx128[1]; i_be2 = idx128[2];
    } else {
        i_b0 = idx64[0]; i_b1 = idx64[1]; i_be0 = idx64[2];
        i_be1 = idx64[3]; i_g0 = idx64[4]; i_g1 = idx64[5];
        i_b2 = idx128[0]; i_be2 = idx128[1]; i_g2 = idx128[2];
    }

    const float* coords   = (const float*)d_in[i_coords];
    const float* features = (const float*)d_in[i_features];
    const float* w0 = (const float*)d_in[i_w0];
    const float* b0 = (const float*)d_in[i_b0];
    const float* g0 = (const float*)d_in[i_g0];
    const float* be0 = (const float*)d_in[i_be0];
    const float* w1 = (const float*)d_in[i_w1];
    const float* b1 = (const float*)d_in[i_b1];
    const float* g1 = (const float*)d_in[i_g1];
    const float* be1 = (const float*)d_in[i_be1];
    const float* w2 = (const float*)d_in[i_w2];
    const float* b2 = (const float*)d_in[i_b2];
    const float* g2 = (const float*)d_in[i_g2];
    const float* be2 = (const float*)d_in[i_be2];
    float* out = (float*)d_out;

    (void)out_size;

    float* y0; float* y1; float* y2; float* gr;
    cudaGetSymbolAddress((void**)&gr, g_grouped);
    cudaGetSymbolAddress((void**)&y0, g_y0);
    cudaGetSymbolAddress((void**)&y1, g_y1);
    cudaGetSymbolAddress((void**)&y2, g_y2);

    zero_stats_kernel<<<1, 512>>>();
    fps_kernel<<<NB * CSZ, 512>>>(coords, out);
    group_kernel<<<NB * NC, 256>>>(coords, features, out, gr);

    gemm_kernel<16, 64, 64, 0, false><<<NROWS / 64, 256>>>(gr, w0, b0, nullptr, nullptr, y0);
    stats_kernel<64, 0><<<256, 256>>>(y0);
    gemm_kernel<64, 64, 64, 0, true><<<NROWS / 64, 256>>>(y0, w1, b1, g0, be0, y1);
    stats_kernel<64, 128><<<256, 256>>>(y1);
    gemm_kernel<64, 128, 32, 128, true><<<NROWS / 32, 256>>>(y1, w2, b2, g1, be1, y2);
    stats_kernel<128, 256><<<256, 256>>>(y2);
    pool_kernel<<<NB * NC, 128>>>(g2, be2, out);
}

// round 16
// speedup vs baseline: 1.4964x; 1.2962x over previous
#include <cuda_runtime.h>
#include <cstdint>

#define NPTS   8192
#define NB     4
#define NC     1024
#define KNN    32
#define DFEAT  13
#define NROWS  (NB*NC*KNN)          // 131072
#define CENT_FLOATS (NB*NC*3)       // 12288

static __device__ float  g_x2[NB*NPTS];
static __device__ float  g_grouped[(size_t)NROWS*16];
static __device__ float  g_y0[(size_t)NROWS*64];
static __device__ float  g_y1[(size_t)NROWS*64];
static __device__ float  g_y2[(size_t)NROWS*128];
// stats: [0:64) s0 [64:128) ss0 [128:192) s1 [192:256) ss1 [256:384) s2 [384:512) ss2
static __device__ double g_stats[512];

__device__ __forceinline__ float f_inf() { return __int_as_float(0x7f800000); }

// packed f32x2 ops (per-lane IEEE rn, identical to scalar __fadd_rn/__fmul_rn).
#define MUL_F32X2(out, a, b) asm("mul.rn.f32x2 %0, %1, %2;" : "=l"(out) : "l"(a), "l"(b))
#define ADD_F32X2(out, a, b) asm("add.rn.f32x2 %0, %1, %2;" : "=l"(out) : "l"(a), "l"(b))
#define PACK_F32X2(out, lo, hi) asm("mov.b64 %0, {%1, %2};" : "=l"(out) : "r"(lo), "r"(hi))
#define UNPACK_F32X2(lo, hi, in) asm("mov.b64 {%0, %1}, %2;" : "=r"(lo), "=r"(hi) : "l"(in))

// ---------------- threefry2x32 (jax partitionable mode) ----------------
__device__ __forceinline__ uint32_t rotl32(uint32_t x, int d) { return (x << d) | (x >> (32 - d)); }

__device__ __forceinline__ void threefry2x32(uint32_t k0, uint32_t k1, uint32_t c0, uint32_t c1,
                                             uint32_t& o0, uint32_t& o1) {
    uint32_t ks0 = k0, ks1 = k1, ks2 = k0 ^ k1 ^ 0x1BD11BDAu;
    uint32_t x0 = c0 + ks0, x1 = c1 + ks1;
#define TF_R(r) { x0 += x1; x1 = rotl32(x1, r); x1 ^= x0; }
#define TF_A TF_R(13) TF_R(15) TF_R(26) TF_R(6)
#define TF_B TF_R(17) TF_R(29) TF_R(16) TF_R(24)
    TF_A; x0 += ks1; x1 += ks2 + 1u;
    TF_B; x0 += ks2; x1 += ks0 + 2u;
    TF_A; x0 += ks0; x1 += ks1 + 3u;
    TF_B; x0 += ks1; x1 += ks2 + 4u;
    TF_A; x0 += ks2; x1 += ks0 + 5u;
#undef TF_A
#undef TF_B
#undef TF_R
    o0 = x0; o1 = x1;
}

// ---------------- FPS: one block per batch, 512 threads x 16 points (R13-proven) ----
// Block 0 also zeroes g_stats (replaces the zero_stats launch).
__global__ __launch_bounds__(512, 1) void fps_kernel(const float* __restrict__ coords,
                                                     float* __restrict__ out_cent) {
    const int b = blockIdx.x;
    const float* cb = coords + (size_t)b * NPTS * 3;
    const int tid = threadIdx.x;
    const int wid = tid >> 5, lane = tid & 31;

    if (b == 0) g_stats[tid] = 0.0;   // 512 entries, 512 threads

    unsigned long long pxp[8], pyp[8], pzp[8];
    float dist[16];
#pragma unroll
    for (int t = 0; t < 16; t++) {
        int p = tid + t * 512;
        float x = cb[3 * p], y = cb[3 * p + 1], z = cb[3 * p + 2];
        dist[t] = f_inf();
        g_x2[b * NPTS + p] = __fadd_rn(__fadd_rn(__fmul_rn(x, x), __fmul_rn(y, y)),
                                       __fmul_rn(z, z));
    }
#pragma unroll
    for (int m = 0; m < 8; m++) {
        int p0 = tid + (2 * m) * 512, p1 = tid + (2 * m + 1) * 512;
        PACK_F32X2(pxp[m], __float_as_uint(cb[3 * p0]),     __float_as_uint(cb[3 * p1]));
        PACK_F32X2(pyp[m], __float_as_uint(cb[3 * p0 + 1]), __float_as_uint(cb[3 * p1 + 1]));
        PACK_F32X2(pzp[m], __float_as_uint(cb[3 * p0 + 2]), __float_as_uint(cb[3 * p1 + 2]));
    }

    __shared__ uint32_t shi[2][16];
    __shared__ uint32_t slo[2][16];

    int f;
    {
        uint32_t k2a, k2b, o0, o1;
        threefry2x32(0u, 42u, 0u, 1u, k2a, k2b);
        threefry2x32(k2a, k2b, 0u, (uint32_t)b, o0, o1);
        f = (int)((o0 ^ o1) & 8191u);
    }

    for (int it = 0; it < NC; ++it) {
        const int buf = it & 1;
        float fx = cb[3 * f], fy = cb[3 * f + 1], fz = cb[3 * f + 2];  // L1 broadcast
        if (tid == 0) {
            float* oc = out_cent + ((size_t)b * NC + it) * 3;
            oc[0] = fx; oc[1] = fy; oc[2] = fz;
        }
        unsigned long long nfx, nfy, nfz;
        {
            uint32_t nx = __float_as_uint(-fx), ny = __float_as_uint(-fy), nz = __float_as_uint(-fz);
            PACK_F32X2(nfx, nx, nx); PACK_F32X2(nfy, ny, ny); PACK_F32X2(nfz, nz, nz);
        }

        float mv = -1.0f;
#pragma unroll
        for (int m = 0; m < 8; m++) {
            unsigned long long dx, dy, dz, xx, yy, zz, s1, d2p;
            ADD_F32X2(dx, pxp[m], nfx);
            ADD_F32X2(dy, pyp[m], nfy);
            ADD_F32X2(dz, pzp[m], nfz);
            MUL_F32X2(xx, dx, dx);
            MUL_F32X2(yy, dy, dy);
            MUL_F32X2(zz, dz, dz);
            ADD_F32X2(s1, xx, yy);
            ADD_F32X2(d2p, s1, zz);
            uint32_t lo, hi;
            UNPACK_F32X2(lo, hi, d2p);
            float a = __uint_as_float(lo), c = __uint_as_float(hi);
            dist[2 * m]     = fminf(dist[2 * m], a);
            dist[2 * m + 1] = fminf(dist[2 * m + 1], c);
            mv = fmaxf(mv, dist[2 * m]);
            mv = fmaxf(mv, dist[2 * m + 1]);
        }
        uint32_t wmv = __reduce_max_sync(0xffffffffu, __float_as_uint(mv));
        uint32_t thr = (wmv >= 8u) ? (wmv - 8u) : 0u;
        float thr_f = __uint_as_float(thr);

        uint32_t best = 0u; uint32_t bidx = 0x7fffffffu;
#pragma unroll
        for (int t = 0; t < 16; t++) {
            if (dist[t] >= thr_f) {
                uint32_t sb = __float_as_uint(__fsqrt_rn(dist[t]));
                if (sb > best) { best = sb; bidx = (uint32_t)(tid + t * 512); }
            }
        }
        uint32_t wmax = __reduce_max_sync(0xffffffffu, best);
        uint32_t cand = (best == wmax) ? bidx : 0xffffffffu;
        uint32_t widx = __reduce_min_sync(0xffffffffu, cand);
        if (lane == 0) { shi[buf][wid] = wmax; slo[buf][wid] = widx; }
        __syncthreads();
        uint32_t v = (lane < 16) ? shi[buf][lane] : 0u;
        uint32_t m = __reduce_max_sync(0xffffffffu, v);
        uint32_t c = (v == m && lane < 16) ? slo[buf][lane] : 0xffffffffu;
        uint32_t g = __reduce_min_sync(0xffffffffu, c);
        f = (int)(g & 0x1fffu);
    }
}

// ---------------- grouping: one block per (b,c) ----------------
__global__ __launch_bounds__(256) void group_kernel(const float* __restrict__ coords,
                                                    const float* __restrict__ features,
                                                    const float* __restrict__ cent,
                                                    float* __restrict__ grouped) {
    const int bc = blockIdx.x;
    const int b = bc >> 10;
    const int tid = threadIdx.x;
    const int wid = tid >> 5, lane = tid & 31;
    const float* cb = coords + (size_t)b * NPTS * 3;
    const float* fb = features + (size_t)b * NPTS * DFEAT;
    const float* x2b = g_x2 + b * NPTS;

    const float cx = cent[3 * bc], cy = cent[3 * bc + 1], cz = cent[3 * bc + 2];
    const float c2 = __fadd_rn(__fadd_rn(__fmul_rn(cx, cx), __fmul_rn(cy, cy)), __fmul_rn(cz, cz));
    const float r2 = 0.04f;

    __shared__ float sval[1024];
    __shared__ int sidx[1024];
    __shared__ int scnt;
    __shared__ int schosen[KNN];

    if (tid == 0) scnt = 0;
    __syncthreads();

    for (int n = tid; n < NPTS; n += 256) {
        float x = cb[3 * n], y = cb[3 * n + 1], z = cb[3 * n + 2];
        float dot = __fmaf_rn(cz, z, __fmaf_rn(cy, y, __fmul_rn(cx, x)));
        float d = __fadd_rn(__fmaf_rn(-2.0f, dot, c2), x2b[n]);
        if (d <= r2) {
            int p = atomicAdd(&scnt, 1);
            if (p < 1024) { sval[p] = d; sidx[p] = n; }
        }
    }
    __syncthreads();
    const int M = min(scnt, 1024);
    const int nsel = min(M, KNN);

    if (wid == 0) {
        for (int round = 0; round < nsel; round++) {
            float bv = f_inf(); int bn = 0x7fffffff; int bj = -1;
            for (int j = lane; j < M; j += 32) {
                float v = sval[j]; int n = sidx[j];
                if (v < bv || (v == bv && n < bn)) { bv = v; bn = n; bj = j; }
            }
            uint32_t vb = __float_as_uint(bv);
            vb = (vb & 0x80000000u) ? ~vb : (vb | 0x80000000u);
            uint32_t vmin = __reduce_min_sync(0xffffffffu, vb);
            uint32_t cand = (vb == vmin) ? (uint32_t)bn : 0xffffffffu;
            uint32_t nwin = __reduce_min_sync(0xffffffffu, cand);
            if (vb == vmin && (uint32_t)bn == nwin) sval[bj] = f_inf();
            if (lane == 0) schosen[round] = (int)nwin;
            __syncwarp();
        }
    }
    __syncthreads();

    if (nsel < KNN && tid == 0) {
        int pos = nsel;
        for (int n = 0; n < NPTS && pos < KNN; n++) {
            float x = cb[3 * n], y = cb[3 * n + 1], z = cb[3 * n + 2];
            float dot = __fmaf_rn(cz, z, __fmaf_rn(cy, y, __fmul_rn(cx, x)));
            float d = __fadd_rn(__fmaf_rn(-2.0f, dot, c2), x2b[n]);
            if (!(d <= r2)) schosen[pos++] = n;
        }
    }
    __syncthreads();

    for (int t = tid; t < KNN * 16; t += 256) {
        int k = t >> 4, fc = t & 15;
        int n = schosen[k];
        float v;
        if (fc < 3) {
            float cen = (fc == 0) ? cx : ((fc == 1) ? cy : cz);
            v = cb[3 * n + fc] - cen;
        } else {
            v = fb[DFEAT * n + fc - 3];
        }
        grouped[((size_t)bc * KNN + k) * 16 + fc] = v;
    }
}

// ---------------- GEMM: register-tiled, k-unroll-4 float4, FUSED stats epilogue ----
// SOUT = stats output offset for this layer's raw conv outputs.
template <int FIN, int FOUT, int ROWS, int SOFF, int SOUT, bool NORM>
__global__ __launch_bounds__(256) void gemm_kernel(const float* __restrict__ X,
                                                   const float* __restrict__ W,
                                                   const float* __restrict__ bias,
                                                   const float* __restrict__ gam,
                                                   const float* __restrict__ bet,
                                                   float* __restrict__ Y) {
    constexpr int VC = FOUT / 8;
    constexpr int RT = ROWS / 32;
    constexpr int XP = FIN + 4;
    static_assert(ROWS * XP >= 16 * FOUT, "sX too small for stats staging");

    __shared__ __align__(16) float sW[FIN * FOUT];
    __shared__ float sB[FOUT];
    __shared__ float sA[FIN], sCc[FIN];
    __shared__ __align__(16) float sX[ROWS * XP];

    const int tid = threadIdx.x;

    for (int i = tid; i < FIN * FOUT; i += 256) {
        int o = i / FIN, k = i % FIN;
        sW[k * FOUT + o] = W[i];
    }
    if (tid < FOUT) sB[tid] = bias[tid];
    if (NORM && tid < FIN) {
        double mu = g_stats[SOFF + tid] / (double)NROWS;
        double var = g_stats[SOFF + FIN + tid] / (double)NROWS - mu * mu;
        float a = (float)(1.0 / sqrt(var + 1e-5)) * gam[tid];
        sA[tid] = a;
        sCc[tid] = bet[tid] - (float)mu * a;
    }
    __syncthreads();

    const float4* xb4 = (const float4*)(X + (size_t)blockIdx.x * ROWS * FIN);
    for (int i = tid; i < ROWS * FIN / 4; i += 256) {
        float4 v = xb4[i];
        int row = i / (FIN / 4), c4 = i % (FIN / 4);
        if (NORM) {
            int ch = c4 * 4;
            v.x = fmaxf(fmaf(v.x, sA[ch],     sCc[ch]),     0.0f);
            v.y = fmaxf(fmaf(v.y, sA[ch + 1], sCc[ch + 1]), 0.0f);
            v.z = fmaxf(fmaf(v.z, sA[ch + 2], sCc[ch + 2]), 0.0f);
            v.w = fmaxf(fmaf(v.w, sA[ch + 3], sCc[ch + 3]), 0.0f);
        }
        *(float4*)&sX[row * XP + c4 * 4] = v;
    }
    __syncthreads();

    const int colg = tid & 7, rowg = tid >> 3;
    const int r0 = rowg * RT;

    float acc[RT][VC];
#pragma unroll
    for (int t = 0; t < RT; t++)
#pragma unroll
        for (int j = 0; j < VC; j++) acc[t][j] = sB[colg * VC + j];

#pragma unroll
    for (int k4 = 0; k4 < FIN; k4 += 4) {
        float4 xv[RT];
#pragma unroll
        for (int t = 0; t < RT; t++)
            xv[t] = *(const float4*)&sX[(r0 + t) * XP + k4];
#pragma unroll
        for (int j4 = 0; j4 < VC / 4; j4++) {
            float4 w0 = *(const float4*)&sW[(k4 + 0) * FOUT + colg * VC + j4 * 4];
            float4 w1 = *(const float4*)&sW[(k4 + 1) * FOUT + colg * VC + j4 * 4];
            float4 w2 = *(const float4*)&sW[(k4 + 2) * FOUT + colg * VC + j4 * 4];
            float4 w3 = *(const float4*)&sW[(k4 + 3) * FOUT + colg * VC + j4 * 4];
#pragma unroll
            for (int t = 0; t < RT; t++) {
                acc[t][j4*4+0] = fmaf(xv[t].x, w0.x, acc[t][j4*4+0]);
                acc[t][j4*4+1] = fmaf(xv[t].x, w0.y, acc[t][j4*4+1]);
                acc[t][j4*4+2] = fmaf(xv[t].x, w0.z, acc[t][j4*4+2]);
                acc[t][j4*4+3] = fmaf(xv[t].x, w0.w, acc[t][j4*4+3]);
                acc[t][j4*4+0] = fmaf(xv[t].y, w1.x, acc[t][j4*4+0]);
                acc[t][j4*4+1] = fmaf(xv[t].y, w1.y, acc[t][j4*4+1]);
                acc[t][j4*4+2] = fmaf(xv[t].y, w1.z, acc[t][j4*4+2]);
                acc[t][j4*4+3] = fmaf(xv[t].y, w1.w, acc[t][j4*4+3]);
                acc[t][j4*4+0] = fmaf(xv[t].z, w2.x, acc[t][j4*4+0]);
                acc[t][j4*4+1] = fmaf(xv[t].z, w2.y, acc[t][j4*4+1]);
                acc[t][j4*4+2] = fmaf(xv[t].z, w2.z, acc[t][j4*4+2]);
                acc[t][j4*4+3] = fmaf(xv[t].z, w2.w, acc[t][j4*4+3]);
                acc[t][j4*4+0] = fmaf(xv[t].w, w3.x, acc[t][j4*4+0]);
                acc[t][j4*4+1] = fmaf(xv[t].w, w3.y, acc[t][j4*4+1]);
                acc[t][j4*4+2] = fmaf(xv[t].w, w3.z, acc[t][j4*4+2]);
                acc[t][j4*4+3] = fmaf(xv[t].w, w3.w, acc[t][j4*4+3]);
            }
        }
    }
#pragma unroll
    for (int t = 0; t < RT; t++) {
        float* yr = Y + ((size_t)blockIdx.x * ROWS + r0 + t) * FOUT + colg * VC;
#pragma unroll
        for (int j4 = 0; j4 < VC / 4; j4++)
            ((float4*)yr)[j4] = make_float4(acc[t][j4 * 4], acc[t][j4 * 4 + 1],
                                            acc[t][j4 * 4 + 2], acc[t][j4 * 4 + 3]);
    }

    // -------- fused stats epilogue: per-channel sum / sumsq of raw conv outputs --------
    float ps[VC], pss[VC];
#pragma unroll
    for (int j = 0; j < VC; j++) { ps[j] = 0.0f; pss[j] = 0.0f; }
#pragma unroll
    for (int t = 0; t < RT; t++)
#pragma unroll
        for (int j = 0; j < VC; j++) {
            float v = acc[t][j];
            ps[j] += v;
            pss[j] = fmaf(v, v, pss[j]);
        }
    // reduce across the 4 row-groups within each warp (lanes l, l^8, l^16 share colg)
#pragma unroll
    for (int off = 8; off <= 16; off <<= 1) {
#pragma unroll
        for (int j = 0; j < VC; j++) {
            ps[j]  += __shfl_xor_sync(0xffffffffu, ps[j],  off);
            pss[j] += __shfl_xor_sync(0xffffffffu, pss[j], off);
        }
    }
    __syncthreads();                 // sX reads done; reuse as staging
    float* sS  = sX;                 // [8 warps][FOUT]
    float* sSS = sX + 8 * FOUT;
    const int w = tid >> 5, l = tid & 31;
    if (l < 8) {
#pragma unroll
        for (int j = 0; j < VC; j++) {
            sS [w * FOUT + l * VC + j] = ps[j];
            sSS[w * FOUT + l * VC + j] = pss[j];
        }
    }
    __syncthreads();
    if (tid < FOUT) {
        float s = 0.0f, ss = 0.0f;
#pragma unroll
        for (int ww = 0; ww < 8; ww++) {
            s  += sS [ww * FOUT + tid];
            ss += sSS[ww * FOUT + tid];
        }
        atomicAdd(&g_stats[SOUT + tid], (double)s);
        atomicAdd(&g_stats[SOUT + FOUT + tid], (double)ss);
    }
}

// ---------------- BN+ReLU+maxpool over K ----------------
__global__ __launch_bounds__(128) void pool_kernel(const float* __restrict__ gam,
                                                   const float* __restrict__ bet,
                                                   float* __restrict__ out) {
    const int bc = blockIdx.x;
    const int o = threadIdx.x;
    double mu = g_stats[256 + o] / (double)NROWS;
    double var = g_stats[384 + o] / (double)NROWS - mu * mu;
    float a = (float)(1.0 / sqrt(var + 1e-5)) * gam[o];
    float c = bet[o] - (float)mu * a;
    float m = 0.0f;
#pragma unroll
    for (int k = 0; k < KNN; k++) {
        float v = g_y2[((size_t)bc * KNN + k) * 128 + o];
        v = fmaxf(fmaf(v, a, c), 0.0f);
        m = fmaxf(m, v);
    }
    out[CENT_FLOATS + (size_t)bc * 128 + o] = m;
}

extern "C" void kernel_launch(void* const* d_in, const int* in_sizes, int n_in,
                              void* d_out, int out_size) {
    // resolve inputs by element count (order-agnostic)
    int i_coords = -1, i_features = -1, i_w0 = -1, i_w1 = -1, i_w2 = -1;
    int idx64[6], n64 = 0;
    int idx128[3], n128 = 0;
    for (int i = 0; i < n_in; i++) {
        int s = in_sizes[i];
        if (s == 98304) i_coords = i;
        else if (s == 425984) i_features = i;
        else if (s == 1024) i_w0 = i;
        else if (s == 4096) i_w1 = i;
        else if (s == 8192) i_w2 = i;
        else if (s == 64 && n64 < 6) idx64[n64++] = i;
        else if (s == 128 && n128 < 3) idx128[n128++] = i;
    }

    int i_b0, i_g0, i_be0, i_b1, i_g1, i_be1, i_b2, i_g2, i_be2;
    if (i_coords == 0) {
        i_b0 = idx64[0]; i_g0 = idx64[1]; i_be0 = idx64[2];
        i_b1 = idx64[3]; i_g1 = idx64[4]; i_be1 = idx64[5];
        i_b2 = idx128[0]; i_g2 = idx128[1]; i_be2 = idx128[2];
    } else {
        i_b0 = idx64[0]; i_b1 = idx64[1]; i_be0 = idx64[2];
        i_be1 = idx64[3]; i_g0 = idx64[4]; i_g1 = idx64[5];
        i_b2 = idx128[0]; i_be2 = idx128[1]; i_g2 = idx128[2];
    }

    const float* coords   = (const float*)d_in[i_coords];
    const float* features = (const float*)d_in[i_features];
    const float* w0 = (const float*)d_in[i_w0];
    const float* b0 = (const float*)d_in[i_b0];
    const float* g0 = (const float*)d_in[i_g0];
    const float* be0 = (const float*)d_in[i_be0];
    const float* w1 = (const float*)d_in[i_w1];
    const float* b1 = (const float*)d_in[i_b1];
    const float* g1 = (const float*)d_in[i_g1];
    const float* be1 = (const float*)d_in[i_be1];
    const float* w2 = (const float*)d_in[i_w2];
    const float* b2 = (const float*)d_in[i_b2];
    const float* g2 = (const float*)d_in[i_g2];
    const float* be2 = (const float*)d_in[i_be2];
    float* out = (float*)d_out;

    (void)out_size;

    float* y0; float* y1; float* y2; float* gr;
    cudaGetSymbolAddress((void**)&gr, g_grouped);
    cudaGetSymbolAddress((void**)&y0, g_y0);
    cudaGetSymbolAddress((void**)&y1, g_y1);
    cudaGetSymbolAddress((void**)&y2, g_y2);

    fps_kernel<<<NB, 512>>>(coords, out);                     // also zeroes g_stats (block 0)
    group_kernel<<<NB * NC, 256>>>(coords, features, out, gr);

    gemm_kernel<16, 64, 64, 0, 0, false><<<NROWS / 64, 256>>>(gr, w0, b0, nullptr, nullptr, y0);
    gemm_kernel<64, 64, 64, 0, 128, true><<<NROWS / 64, 256>>>(y0, w1, b1, g0, be0, y1);
    gemm_kernel<64, 128, 32, 128, 256, true><<<NROWS / 32, 256>>>(y1, w2, b2, g1, be1, y2);
    pool_kernel<<<NB * NC, 128>>>(g2, be2, out);
}